// round 2
// baseline (speedup 1.0000x reference)
#include <cuda_runtime.h>
#include <cstdint>

// LinearQuantileRegression: per-sample nearest neighbor over quantile surface.
//   y      : [B, 2]        float32
//   Y_surf : [B, 2, G]     float32  (G = 2500)
//   U_grid : [2, G]        float32
//   out    : [B, 2]        float32, out[b,:] = U_grid[:, argmin_g ||Y_surf[b,:,g]-y[b,:]||^2]
//
// Strategy: one CTA per sample, coalesced float4 streaming of the two G-length
// rows, argmin packed into u64 (d2 bits high, index low) for first-index
// tie-break, warp+block reduction.

#ifndef QBLOCK
#define QBLOCK 256
#endif

__device__ __forceinline__ unsigned long long pack_d2_idx(float d2, unsigned g) {
    // d2 >= 0 always, so IEEE bits order == unsigned order.
    return (((unsigned long long)__float_as_uint(d2)) << 32) | (unsigned long long)g;
}

__global__ __launch_bounds__(QBLOCK, 8)
void lqr_argmin_kernel(const float* __restrict__ y,
                       const float* __restrict__ Ysurf,
                       const float* __restrict__ Ugrid,
                       float* __restrict__ out,
                       int G)
{
    const int b = blockIdx.x;
    const int tid = threadIdx.x;

    const float y0 = y[2 * b + 0];
    const float y1 = y[2 * b + 1];

    // Row base pointers for this sample. G*4 bytes = 10000 B, which is
    // 16-byte aligned, so float4 loads are legal for every row.
    const float4* __restrict__ r0 =
        reinterpret_cast<const float4*>(Ysurf + (size_t)b * 2 * G);
    const float4* __restrict__ r1 =
        reinterpret_cast<const float4*>(Ysurf + (size_t)b * 2 * G + G);

    const int nvec = G >> 2;  // 625

    unsigned long long best = ~0ull;

    for (int i = tid; i < nvec; i += QBLOCK) {
        float4 a = r0[i];
        float4 c = r1[i];
        float dx, dy, d2;
        unsigned g = (unsigned)(i << 2);

        dx = a.x - y0; dy = c.x - y1; d2 = fmaf(dx, dx, dy * dy);
        { unsigned long long p = pack_d2_idx(d2, g + 0); best = min(best, p); }
        dx = a.y - y0; dy = c.y - y1; d2 = fmaf(dx, dx, dy * dy);
        { unsigned long long p = pack_d2_idx(d2, g + 1); best = min(best, p); }
        dx = a.z - y0; dy = c.z - y1; d2 = fmaf(dx, dx, dy * dy);
        { unsigned long long p = pack_d2_idx(d2, g + 2); best = min(best, p); }
        dx = a.w - y0; dy = c.w - y1; d2 = fmaf(dx, dx, dy * dy);
        { unsigned long long p = pack_d2_idx(d2, g + 3); best = min(best, p); }
    }

    // Warp reduction
    #pragma unroll
    for (int off = 16; off > 0; off >>= 1) {
        unsigned long long o = __shfl_down_sync(0xffffffffu, best, off);
        best = min(best, o);
    }

    // Cross-warp reduction
    __shared__ unsigned long long smin[QBLOCK / 32];
    const int lane = tid & 31;
    const int wid = tid >> 5;
    if (lane == 0) smin[wid] = best;
    __syncthreads();

    if (wid == 0) {
        best = (lane < (QBLOCK / 32)) ? smin[lane] : ~0ull;
        #pragma unroll
        for (int off = (QBLOCK / 64); off > 0; off >>= 1) {
            unsigned long long o = __shfl_down_sync(0xffffffffu, best, off);
            best = min(best, o);
        }
        if (lane == 0) {
            const unsigned idx = (unsigned)(best & 0xffffffffu);
            out[2 * b + 0] = Ugrid[idx];
            out[2 * b + 1] = Ugrid[G + idx];
        }
    }
}

extern "C" void kernel_launch(void* const* d_in, const int* in_sizes, int n_in,
                              void* d_out, int out_size)
{
    const float* y     = (const float*)d_in[0];   // [B, 2]
    const float* Ysurf = (const float*)d_in[1];   // [B, 2, G]
    const float* Ugrid = (const float*)d_in[2];   // [2, G]
    float* out = (float*)d_out;                   // [B, 2]

    const int B = in_sizes[0] / 2;
    const int G = in_sizes[2] / 2;

    lqr_argmin_kernel<<<B, QBLOCK>>>(y, Ysurf, Ugrid, out, G);
}

// round 5
// speedup vs baseline: 1.0144x; 1.0144x over previous
#include <cuda_runtime.h>
#include <cstdint>

// LinearQuantileRegression nearest-neighbor argmin, warp-per-sample.
//   y      : [B, 2]     float32
//   Y_surf : [B, 2, G]  float32  (G = 2500)
//   U_grid : [2, G]     float32
//   out    : [B, 2]     float32
//
// Each warp owns one sample b: streams the two G-length rows with
// streaming (evict-first) float4 loads, 2x unrolled for MLP=4 per thread,
// packs (d2_bits << 32 | g) into u64 so min() gives argmin with
// first-index tie-break, then a single warp shuffle reduction.

#ifndef QBLOCK
#define QBLOCK 256   // 8 warps -> 8 samples per CTA
#endif

__device__ __forceinline__ unsigned long long pack_d2_idx(float d2, unsigned g) {
    // d2 >= 0 so IEEE-754 bit pattern order == unsigned order.
    return (((unsigned long long)__float_as_uint(d2)) << 32) | (unsigned long long)g;
}

__device__ __forceinline__ void accum4(unsigned long long& best,
                                       float4 a, float4 c,
                                       float y0, float y1, unsigned g) {
    float dx, dy, d2;
    dx = a.x - y0; dy = c.x - y1; d2 = fmaf(dx, dx, dy * dy);
    best = min(best, pack_d2_idx(d2, g + 0));
    dx = a.y - y0; dy = c.y - y1; d2 = fmaf(dx, dx, dy * dy);
    best = min(best, pack_d2_idx(d2, g + 1));
    dx = a.z - y0; dy = c.z - y1; d2 = fmaf(dx, dx, dy * dy);
    best = min(best, pack_d2_idx(d2, g + 2));
    dx = a.w - y0; dy = c.w - y1; d2 = fmaf(dx, dx, dy * dy);
    best = min(best, pack_d2_idx(d2, g + 3));
}

__global__ __launch_bounds__(QBLOCK)
void lqr_warp_kernel(const float* __restrict__ y,
                     const float* __restrict__ Ysurf,
                     const float* __restrict__ Ugrid,
                     float* __restrict__ out,
                     int G, int B)
{
    const int warps_per_cta = QBLOCK >> 5;
    const int b = blockIdx.x * warps_per_cta + (threadIdx.x >> 5);
    if (b >= B) return;
    const int lane = threadIdx.x & 31;

    const float2 yv = *reinterpret_cast<const float2*>(y + 2 * b);
    const float y0 = yv.x;
    const float y1 = yv.y;

    // Row bases: b*2*G and b*2*G + G floats. G*4 = 10000 bytes, 16B aligned,
    // so float4 views are legal for every row.
    const float4* __restrict__ r0 =
        reinterpret_cast<const float4*>(Ysurf + (size_t)b * 2 * G);
    const float4* __restrict__ r1 =
        reinterpret_cast<const float4*>(Ysurf + (size_t)b * 2 * G + G);

    const int nvec = G >> 2;  // 625

    unsigned long long best = ~0ull;

    int i = lane;
    // 2x unrolled main loop: 4 independent 16B streaming loads in flight.
    for (; i + 32 < nvec; i += 64) {
        float4 a0 = __ldcs(&r0[i]);
        float4 c0 = __ldcs(&r1[i]);
        float4 a1 = __ldcs(&r0[i + 32]);
        float4 c1 = __ldcs(&r1[i + 32]);
        accum4(best, a0, c0, y0, y1, (unsigned)(i << 2));
        accum4(best, a1, c1, y0, y1, (unsigned)((i + 32) << 2));
    }
    if (i < nvec) {
        float4 a0 = __ldcs(&r0[i]);
        float4 c0 = __ldcs(&r1[i]);
        accum4(best, a0, c0, y0, y1, (unsigned)(i << 2));
    }

    // Warp argmin reduction.
    #pragma unroll
    for (int off = 16; off > 0; off >>= 1) {
        unsigned long long o = __shfl_down_sync(0xffffffffu, best, off);
        best = min(best, o);
    }

    if (lane == 0) {
        const unsigned idx = (unsigned)(best & 0xffffffffu);
        float2 u;
        u.x = __ldg(&Ugrid[idx]);
        u.y = __ldg(&Ugrid[G + idx]);
        *reinterpret_cast<float2*>(out + 2 * b) = u;
    }
}

extern "C" void kernel_launch(void* const* d_in, const int* in_sizes, int n_in,
                              void* d_out, int out_size)
{
    const float* y     = (const float*)d_in[0];   // [B, 2]
    const float* Ysurf = (const float*)d_in[1];   // [B, 2, G]
    const float* Ugrid = (const float*)d_in[2];   // [2, G]
    float* out = (float*)d_out;                   // [B, 2]

    const int B = in_sizes[0] / 2;
    const int G = in_sizes[2] / 2;

    const int warps_per_cta = QBLOCK / 32;
    const int grid = (B + warps_per_cta - 1) / warps_per_cta;

    lqr_warp_kernel<<<grid, QBLOCK>>>(y, Ysurf, Ugrid, out, G, B);
}